// round 15
// baseline (speedup 1.0000x reference)
#include <cuda_runtime.h>
#include <cuda_fp16.h>
#include <math.h>
#include <stdint.h>

// Problem constants
#define BB   8
#define NN   4096
#define CC   768
#define HH   8
#define HD   96
#define MROWS (BB*NN)      // 32768
#define K3C   (3*CC)       // 2304
#define BHD   (BB*HH*HD)   // 6144

// ---------------- scratch (device globals; no allocs allowed) ----------------
__device__ __align__(256) __half g_xh[MROWS*CC];         // fp16 copy of x
__device__ __align__(256) __half g_wqkvh[K3C*CC];        // fp16 w_qkv
__device__ __align__(256) __half g_wprojh[CC*CC];        // fp16 w_proj
__device__ __align__(256) __half g_qh[BB*HH*HD*NN];      // [b][h][d][n]
__device__ __align__(256) __half g_kh[BB*HH*HD*NN];
__device__ __align__(256) __half g_vh[BB*HH*HD*NN];
__device__ __align__(256) float g_nq[BHD];               // sum-of-squares accum
__device__ __align__(256) float g_nk[BHD];
__device__ __align__(256) float g_gram[BB*HH*HD*HD];     // fp32 accumulators
__device__ __align__(256) __half g_attn[BB*HH*HD*HD];    // softmaxed, fp16
__device__ __align__(256) __half g_aoh[MROWS*CC];        // attention out, fp16

// ======================= helpers =======================
__device__ __forceinline__ uint32_t smem_u32(const void* p) {
    uint32_t a;
    asm("{ .reg .u64 t; cvta.to.shared.u64 t, %1; cvt.u32.u64 %0, t; }"
        : "=r"(a) : "l"(p));
    return a;
}
__device__ __forceinline__ void ldm_x4(uint32_t* r, uint32_t addr) {
    asm volatile("ldmatrix.sync.aligned.m8n8.x4.shared.b16 {%0,%1,%2,%3}, [%4];"
        : "=r"(r[0]), "=r"(r[1]), "=r"(r[2]), "=r"(r[3]) : "r"(addr));
}
__device__ __forceinline__ void ldm_x2(uint32_t* r, uint32_t addr) {
    asm volatile("ldmatrix.sync.aligned.m8n8.x2.shared.b16 {%0,%1}, [%2];"
        : "=r"(r[0]), "=r"(r[1]) : "r"(addr));
}
__device__ __forceinline__ void ldm_x4_trans(uint32_t* r, uint32_t addr) {
    asm volatile("ldmatrix.sync.aligned.m8n8.x4.trans.shared.b16 {%0,%1,%2,%3}, [%4];"
        : "=r"(r[0]), "=r"(r[1]), "=r"(r[2]), "=r"(r[3]) : "r"(addr));
}
__device__ __forceinline__ void mma_fp16(float* c, const uint32_t* a, const uint32_t* b) {
    asm volatile("mma.sync.aligned.m16n8k16.row.col.f32.f16.f16.f32 "
        "{%0,%1,%2,%3}, {%4,%5,%6,%7}, {%8,%9}, {%0,%1,%2,%3};"
        : "+f"(c[0]), "+f"(c[1]), "+f"(c[2]), "+f"(c[3])
        : "r"(a[0]), "r"(a[1]), "r"(a[2]), "r"(a[3]), "r"(b[0]), "r"(b[1]));
}
__device__ __forceinline__ void cp16(uint32_t s, const void* g) {
    asm volatile("cp.async.cg.shared.global [%0], [%1], 16;" :: "r"(s), "l"(g));
}
#define CP_COMMIT() asm volatile("cp.async.commit_group;" ::: "memory")
#define CP_WAIT1()  asm volatile("cp.async.wait_group 1;" ::: "memory")
#define CP_WAIT0()  asm volatile("cp.async.wait_group 0;" ::: "memory")

// ======================= prep: f2h convert + zero accumulators ==============
#define NX4  (MROWS*CC/4)     // 6291456
#define NWQ4 (K3C*CC/4)       // 442368
#define NWP4 (CC*CC/4)        // 147456
__global__ void prep_kernel(const float* __restrict__ x,
                            const float* __restrict__ wq,
                            const float* __restrict__ wp) {
    int i = blockIdx.x * blockDim.x + threadIdx.x;
    if (i < BB*HH*HD*HD) g_gram[i] = 0.0f;
    if (i < BHD) { g_nq[i] = 0.0f; g_nk[i] = 0.0f; }
    const float* src;
    __half* dst;
    int off;
    if (i < NX4) { src = x; dst = g_xh; off = i; }
    else if (i < NX4 + NWQ4) { src = wq; dst = g_wqkvh; off = i - NX4; }
    else if (i < NX4 + NWQ4 + NWP4) { src = wp; dst = g_wprojh; off = i - NX4 - NWQ4; }
    else return;
    float4 v = ((const float4*)src)[off];
    __half2 a = __float22half2_rn(make_float2(v.x, v.y));
    __half2 b = __float22half2_rn(make_float2(v.z, v.w));
    uint2 u;
    u.x = *reinterpret_cast<uint32_t*>(&a);
    u.y = *reinterpret_cast<uint32_t*>(&b);
    ((uint2*)dst)[off] = u;
}

// ======================= fp16 GEMM mainloop: 128x128, KC=64, 3-stage ========
#define PH 72
#define TSZH (128*PH*2)      // 18432 B
#define STAGEH (2*TSZH)      // 36864 B (A + B)
#define NSTG 3
#define DSMEMH (NSTG*STAGEH) // 110592 B
#define KCH 64
#define NCHH (CC/KCH)        // 12

__device__ __forceinline__ void issue_chunk(
    const __half* __restrict__ A, const __half* __restrict__ B,
    int m0, int n0, int k0, uint32_t st, int tid)
{
#pragma unroll
    for (int p = 0; p < 4; p++) {
        int slot = tid + p * 256;          // 0..1023
        int row = slot >> 3, c = slot & 7;
        cp16(st + row * (PH * 2) + c * 16,
             A + (size_t)(m0 + row) * CC + k0 + c * 8);
        cp16(st + TSZH + row * (PH * 2) + c * 16,
             B + (size_t)(n0 + row) * CC + k0 + c * 8);
    }
}

__device__ __forceinline__ void mma_mainloop_h(
    const __half* __restrict__ A, const __half* __restrict__ B,
    int m0, int n0, float acc[4][4][4], char* sm)
{
    const int tid = threadIdx.x;
    const int wid = tid >> 5, lane = tid & 31;
    const int wm = (wid >> 2) * 64;
    const int wn = (wid & 3) * 32;
    const uint32_t sbase = smem_u32(sm);
    const uint32_t a_l = (uint32_t)(wm + (lane & 15)) * (PH * 2) + ((lane >> 4) << 4);
    const uint32_t b_l = (uint32_t)(wn + (lane & 7) + ((lane >> 4) & 1) * 8) * (PH * 2)
                       + (((lane >> 3) & 1) << 4);

    issue_chunk(A, B, m0, n0, 0, sbase, tid);
    CP_COMMIT();
    issue_chunk(A, B, m0, n0, KCH, sbase + STAGEH, tid);
    CP_COMMIT();

    for (int c = 0; c < NCHH; c++) {
        if (c == NCHH - 1) { CP_WAIT0(); } else { CP_WAIT1(); }
        __syncthreads();
        if (c + 2 < NCHH) {
            issue_chunk(A, B, m0, n0, (c + 2) * KCH,
                        sbase + (uint32_t)((c + 2) % NSTG) * STAGEH, tid);
            CP_COMMIT();
        }
        const uint32_t st = sbase + (uint32_t)(c % NSTG) * STAGEH;
#pragma unroll
        for (int kk = 0; kk < 4; kk++) {
            uint32_t ah[4][4], bh[2][4];
#pragma unroll
            for (int i = 0; i < 4; i++)
                ldm_x4(ah[i], st + a_l + kk * 32 + i * 16 * (PH * 2));
#pragma unroll
            for (int j = 0; j < 2; j++)
                ldm_x4(bh[j], st + TSZH + b_l + kk * 32 + j * 16 * (PH * 2));
#pragma unroll
            for (int i = 0; i < 4; i++)
#pragma unroll
                for (int j4 = 0; j4 < 4; j4++)
                    mma_fp16(acc[i][j4], ah[i], &bh[j4 >> 1][(j4 & 1) * 2]);
        }
    }
}

// ---- QKV GEMM: M = qkv features, N = tokens; scatter fp16 + fused norm ----
__global__ __launch_bounds__(256, 2) void gemm_qkv_mma(void) {
    extern __shared__ char sm[];
    const int m0 = blockIdx.x * 128;
    const int n0 = blockIdx.y * 128;
    float acc[4][4][4];
#pragma unroll
    for (int i = 0; i < 4; i++)
#pragma unroll
        for (int j = 0; j < 4; j++)
#pragma unroll
            for (int r = 0; r < 4; r++) acc[i][j][r] = 0.0f;

    mma_mainloop_h(g_wqkvh, g_xh, m0, n0, acc, sm);

    const int tid = threadIdx.x;
    const int wid = tid >> 5, lane = tid & 31;
    const int wm = (wid >> 2) * 64, wn = (wid & 3) * 32;
    const int b = n0 >> 12;
    const int ntk = (n0 & (NN - 1)) + wn + (lane & 3) * 2;
#pragma unroll
    for (int i = 0; i < 4; i++) {
#pragma unroll
        for (int half = 0; half < 2; half++) {
            int f = m0 + wm + i * 16 + (lane >> 2) + half * 8;
            int t = f / CC;
            int rem = f - t * CC;
            int h = rem / HD, d = rem - h * HD;
            __half* dst = (t == 0) ? g_qh : (t == 1) ? g_kh : g_vh;
            __half* rowp = dst + ((size_t)(b * HH + h) * HD + d) * NN;
            float ssum = 0.0f;
#pragma unroll
            for (int j4 = 0; j4 < 4; j4++) {
                float v0 = acc[i][j4][half * 2], v1 = acc[i][j4][half * 2 + 1];
                *(__half2*)&rowp[ntk + j4 * 8] = __floats2half2_rn(v0, v1);
                ssum += v0 * v0 + v1 * v1;
            }
            if (t < 2) {
                ssum += __shfl_xor_sync(0xffffffff, ssum, 1);
                ssum += __shfl_xor_sync(0xffffffff, ssum, 2);
                if ((lane & 3) == 0)
                    atomicAdd(&((t == 0) ? g_nq : g_nk)[(b * HH + h) * HD + d], ssum);
            }
        }
    }
}

// ---- Proj GEMM: M = tokens (g_aoh), N = out features; out fp32 coalesced ----
__global__ __launch_bounds__(256, 2) void gemm_proj_mma(
    const float* __restrict__ bias, float* __restrict__ out)
{
    extern __shared__ char sm[];
    const int n0 = blockIdx.x * 128;
    const int m0 = blockIdx.y * 128;
    float acc[4][4][4];
#pragma unroll
    for (int i = 0; i < 4; i++)
#pragma unroll
        for (int j = 0; j < 4; j++)
#pragma unroll
            for (int r = 0; r < 4; r++) acc[i][j][r] = 0.0f;

    mma_mainloop_h(g_aoh, g_wprojh, m0, n0, acc, sm);

    const int tid = threadIdx.x;
    const int wid = tid >> 5, lane = tid & 31;
    const int wm = (wid >> 2) * 64, wn = (wid & 3) * 32;
    float2 bv[4];
#pragma unroll
    for (int j4 = 0; j4 < 4; j4++)
        bv[j4] = *(const float2*)&bias[n0 + wn + j4 * 8 + (lane & 3) * 2];
#pragma unroll
    for (int i = 0; i < 4; i++) {
#pragma unroll
        for (int half = 0; half < 2; half++) {
            int tok = m0 + wm + i * 16 + (lane >> 2) + half * 8;
            float* rowp = out + (size_t)tok * CC + n0 + wn + (lane & 3) * 2;
#pragma unroll
            for (int j4 = 0; j4 < 4; j4++) {
                *(float2*)&rowp[j4 * 8] =
                    make_float2(acc[i][j4][half * 2] + bv[j4].x,
                                acc[i][j4][half * 2 + 1] + bv[j4].y);
            }
        }
    }
}

// ---------------- Gram via mma (ksplit 16, register-prefetch) ----------------
#define GP 72
__global__ __launch_bounds__(256) void gram_mma() {
    const int bh = blockIdx.y;
    const int kseg = blockIdx.x;
    const __half* qb = g_qh + (size_t)bh * HD * NN;
    const __half* kb = g_kh + (size_t)bh * HD * NN;
    __shared__ __half qs[96 * GP];
    __shared__ __half ks[96 * GP];
    const int tid = threadIdx.x;
    const int wid = tid >> 5, lane = tid & 31;
    const int wm = (wid >> 2) * 48;
    const int wn = (wid & 3) * 24;
    const uint32_t qsb = smem_u32(qs), ksb = smem_u32(ks);
    const uint32_t a_base = qsb + ((wm + (lane & 15)) * GP + (lane >> 4) * 8) * 2;
    const uint32_t b_base = ksb + ((wn + (lane & 7)) * GP + ((lane >> 3) & 1) * 8) * 2;

    float acc[3][3][4];
#pragma unroll
    for (int i = 0; i < 3; i++)
#pragma unroll
        for (int j = 0; j < 3; j++)
#pragma unroll
            for (int r = 0; r < 4; r++) acc[i][j][r] = 0.0f;

    uint4 rg[6];
#pragma unroll
    for (int l = 0; l < 6; l++) {
        int idx = l * 256 + tid;
        int row = idx >> 4, s = idx & 15;
        rg[l] = (s < 8)
            ? *(const uint4*)&qb[(size_t)row * NN + kseg * 256 + s * 8]
            : *(const uint4*)&kb[(size_t)row * NN + kseg * 256 + (s - 8) * 8];
    }

    for (int it = 0; it < 4; it++) {
#pragma unroll
        for (int l = 0; l < 6; l++) {
            int idx = l * 256 + tid;
            int row = idx >> 4, s = idx & 15;
            if (s < 8) *(uint4*)&qs[row * GP + s * 8] = rg[l];
            else       *(uint4*)&ks[row * GP + (s - 8) * 8] = rg[l];
        }
        __syncthreads();
        if (it < 3) {
            int k0 = kseg * 256 + (it + 1) * 64;
#pragma unroll
            for (int l = 0; l < 6; l++) {
                int idx = l * 256 + tid;
                int row = idx >> 4, s = idx & 15;
                rg[l] = (s < 8)
                    ? *(const uint4*)&qb[(size_t)row * NN + k0 + s * 8]
                    : *(const uint4*)&kb[(size_t)row * NN + k0 + (s - 8) * 8];
            }
        }
#pragma unroll
        for (int kk = 0; kk < 4; kk++) {
            uint32_t a[3][4], bfr[3][2];
#pragma unroll
            for (int i = 0; i < 3; i++)
                ldm_x4(a[i], a_base + i * 16 * GP * 2 + kk * 32);
#pragma unroll
            for (int j = 0; j < 3; j++)
                ldm_x2(bfr[j], b_base + j * 8 * GP * 2 + kk * 32);
#pragma unroll
            for (int i = 0; i < 3; i++)
#pragma unroll
                for (int j = 0; j < 3; j++)
                    mma_fp16(acc[i][j], a[i], bfr[j]);
        }
        __syncthreads();
    }
    float* G = g_gram + (size_t)bh * HD * HD;
#pragma unroll
    for (int i = 0; i < 3; i++) {
        int d = wm + i * 16 + (lane >> 2);
#pragma unroll
        for (int j = 0; j < 3; j++) {
            int e = wn + j * 8 + (lane & 3) * 2;
            atomicAdd(&G[d * HD + e],       acc[i][j][0]);
            atomicAdd(&G[d * HD + e + 1],   acc[i][j][1]);
            atomicAdd(&G[(d + 8) * HD + e],     acc[i][j][2]);
            atomicAdd(&G[(d + 8) * HD + e + 1], acc[i][j][3]);
        }
    }
}

// ---------------- scale + softmax, warp-per-row, emit fp16 attn ------------
__global__ void softmax_kernel(const float* __restrict__ temp) {
    const int bh = blockIdx.x;
    const int h = bh & (HH - 1);
    const int wid = threadIdx.x >> 5, lane = threadIdx.x & 31;
    const int d = blockIdx.y * 8 + wid;            // grid.y = 12, 8 warps/block
    const float* row = g_gram + (size_t)bh * HD * HD + d * HD;
    __half* orow = g_attn + (size_t)bh * HD * HD + d * HD;
    const float nq = fmaxf(sqrtf(fmaxf(g_nq[bh * HD + d], 0.0f)), 1e-12f);
    const float scale = temp[h] / nq;

    float v[3];
    float mx = -1e30f;
#pragma unroll
    for (int j = 0; j < 3; j++) {
        int e = lane + j * 32;
        float rk = fmaxf(sqrtf(fmaxf(g_nk[bh * HD + e], 0.0f)), 1e-12f);
        v[j] = row[e] * scale / rk;
        mx = fmaxf(mx, v[j]);
    }
#pragma unroll
    for (int o = 16; o; o >>= 1) mx = fmaxf(mx, __shfl_xor_sync(0xffffffff, mx, o));
    float s = 0.0f;
#pragma unroll
    for (int j = 0; j < 3; j++) {
        v[j] = expf(v[j] - mx);
        s += v[j];
    }
#pragma unroll
    for (int o = 16; o; o >>= 1) s += __shfl_xor_sync(0xffffffff, s, o);
    float inv = 1.0f / s;
#pragma unroll
    for (int j = 0; j < 3; j++) orow[lane + j * 32] = __float2half(v[j] * inv);
}

// ---- AV via mma: 256-token tiles, double-buffered cp.async v sub-tiles -----
#define AP 104                    // attn smem pitch (halves)
#define VPH 136                   // v smem pitch (halves), 128-token sub-tile
#define ASZ2 (96*AP*2)            // 19968 B
#define VSZ2 (96*VPH*2)           // 26112 B per buffer
#define AVDSM (ASZ2 + 2*VSZ2)     // 72192 B dynamic
#define OPD2 96                   // output stage pitch (halves): 192 B, 16B-aligned
__global__ __launch_bounds__(256) void av_mma() {
    extern __shared__ __align__(16) char smb[];
    const int bh = blockIdx.y;
    const int n0 = blockIdx.x * 256;
    const int b = bh >> 3, h = bh & 7;
    __half* as_t = (__half*)smb;                       // [96][AP]
    const uint32_t sbase = smem_u32(smb);
    const uint32_t vbase0 = sbase + ASZ2;
    const int tid = threadIdx.x;
    const int wid = tid >> 5, lane = tid & 31;
    const int wm = (wid >> 2) * 48;
    const int wn = (wid & 3) * 32;

    const __half* vb = g_vh + (size_t)bh * HD * NN;
    // issue v sub-tile 0 (96x128 halves)
#pragma unroll
    for (int l = 0; l < 6; l++) {
        int idx = l * 256 + tid;           // 1536 slots = 96 rows x 16 uint4
        int row = idx >> 4, c = idx & 15;
        cp16(vbase0 + row * (VPH * 2) + c * 16, &vb[(size_t)row * NN + n0 + c * 8]);
    }
    CP_COMMIT();
    // attn tile (synchronous, overlaps v0 flight)
    const __half* at = g_attn + (size_t)bh * HD * HD;
#pragma unroll
    for (int l = 0; l < 5; l++) {
        int idx = l * 256 + tid;
        if (idx < 1152) {
            int row = idx / 12, c = idx % 12;
            *(uint4*)&as_t[row * AP + c * 8] = *(const uint4*)&at[row * HD + c * 8];
        }
    }
    // issue v sub-tile 1
#pragma unroll
    for (int l = 0; l < 6; l++) {
        int idx = l * 256 + tid;
        int row = idx >> 4, c = idx & 15;
        cp16(vbase0 + VSZ2 + row * (VPH * 2) + c * 16,
             &vb[(size_t)row * NN + n0 + 128 + c * 8]);
    }
    CP_COMMIT();

    const uint32_t a_base = sbase + ((wm + (lane & 15)) * AP + (lane >> 4) * 8) * 2;
    const uint32_t b_roff = ((lane & 7) + ((lane >> 3) & 1) * 8) * VPH * 2;
    const uint32_t b_coff = (wn + ((lane >> 4) & 1) * 8) * 2;

#pragma unroll
    for (int sub = 0; sub < 2; sub++) {
        if (sub == 0) { CP_WAIT1(); } else { CP_WAIT0(); }
        __syncthreads();
        const uint32_t vsb = vbase0 + (uint32_t)sub * VSZ2;

        float acc[3][4][4];
#pragma unroll
        for (int i = 0; i < 3; i++)
#pragma unroll
            for (int j = 0; j < 4; j++)
#pragma unroll
                for (int r = 0; r < 4; r++) acc[i][j][r] = 0.0f;

#pragma unroll
        for (int kk = 0; kk < 6; kk++) {
            uint32_t a[3][4], bt[2][4];
#pragma unroll
            for (int i = 0; i < 3; i++)
                ldm_x4(a[i], a_base + i * 16 * AP * 2 + kk * 32);
#pragma unroll
            for (int j = 0; j < 2; j++)
                ldm_x4_trans(bt[j], vsb + (kk * 16) * VPH * 2 + b_roff + b_coff + j * 32);
#pragma unroll
            for (int i = 0; i < 3; i++)
#pragma unroll
                for (int jn = 0; jn < 4; jn++)
                    mma_fp16(acc[i][jn], a[i], &bt[jn >> 1][(jn & 1) * 2]);
        }

        // stage [n][d] into the just-consumed v buffer (dead data), then store
        __syncthreads();
        __half* ot = (__half*)(smb + ASZ2 + sub * VSZ2);   // [128][OPD2]
#pragma unroll
        for (int i = 0; i < 3; i++) {
#pragma unroll
            for (int half = 0; half < 2; half++) {
                int d = wm + i * 16 + (lane >> 2) + half * 8;
#pragma unroll
                for (int jn = 0; jn < 4; jn++) {
                    int nl = wn + jn * 8 + (lane & 3) * 2;
                    ot[nl * OPD2 + d]       = __float2half(acc[i][jn][half * 2]);
                    ot[(nl + 1) * OPD2 + d] = __float2half(acc[i][jn][half * 2 + 1]);
                }
            }
        }
        __syncthreads();
#pragma unroll
        for (int l = 0; l < 6; l++) {
            int idx = l * 256 + tid;       // 1536 = 128 rows x 12 octs
            int row = idx / 12, c = idx % 12;
            *(uint4*)&g_aoh[((size_t)(b * NN + n0 + sub * 128 + row)) * CC + h * HD + c * 8] =
                *(uint4*)&ot[row * OPD2 + c * 8];
        }
    }
}

// ---------------- launch ----------------
extern "C" void kernel_launch(void* const* d_in, const int* in_sizes, int n_in,
                              void* d_out, int out_size)
{
    const float* x      = (const float*)d_in[0];
    const float* w_qkv  = (const float*)d_in[1];
    const float* temp   = (const float*)d_in[2];
    const float* w_proj = (const float*)d_in[3];
    const float* b_proj = (const float*)d_in[4];
    float* out = (float*)d_out;

    cudaFuncSetAttribute(gemm_qkv_mma, cudaFuncAttributeMaxDynamicSharedMemorySize, DSMEMH);
    cudaFuncSetAttribute(gemm_proj_mma, cudaFuncAttributeMaxDynamicSharedMemorySize, DSMEMH);
    cudaFuncSetAttribute(av_mma, cudaFuncAttributeMaxDynamicSharedMemorySize, AVDSM);

    prep_kernel<<<(NX4 + NWQ4 + NWP4 + 255) / 256, 256>>>(x, w_qkv, w_proj);
    gemm_qkv_mma<<<dim3(K3C / 128, MROWS / 128), 256, DSMEMH>>>();
    gram_mma<<<dim3(16, BB * HH), 256>>>();
    softmax_kernel<<<dim3(BB * HH, 12), 256>>>(temp);
    av_mma<<<dim3(NN / 256, BB * HH), 256, AVDSM>>>();
    gemm_proj_mma<<<dim3(CC / 128, MROWS / 128), 256, DSMEMH>>>(b_proj, out);
}

// round 16
// speedup vs baseline: 1.0174x; 1.0174x over previous
#include <cuda_runtime.h>
#include <cuda_fp16.h>
#include <math.h>
#include <stdint.h>

// Problem constants
#define BB   8
#define NN   4096
#define CC   768
#define HH   8
#define HD   96
#define MROWS (BB*NN)      // 32768
#define K3C   (3*CC)       // 2304
#define BHD   (BB*HH*HD)   // 6144

// ---------------- scratch (device globals; no allocs allowed) ----------------
__device__ __align__(256) __half g_xh[MROWS*CC];         // fp16 copy of x
__device__ __align__(256) __half g_wqkvh[K3C*CC];        // fp16 w_qkv
__device__ __align__(256) __half g_wprojh[CC*CC];        // fp16 w_proj
__device__ __align__(256) __half g_qh[BB*HH*HD*NN];      // [b][h][d][n]
__device__ __align__(256) __half g_kh[BB*HH*HD*NN];
__device__ __align__(256) __half g_vh[BB*HH*HD*NN];
__device__ __align__(256) float g_nq[BHD];               // sum-of-squares accum
__device__ __align__(256) float g_nk[BHD];
__device__ __align__(256) float g_gram[BB*HH*HD*HD];     // fp32 accumulators
__device__ __align__(256) __half g_attn[BB*HH*HD*HD];    // softmaxed, fp16
__device__ __align__(256) __half g_aoh[MROWS*CC];        // attention out, fp16

// ======================= helpers =======================
__device__ __forceinline__ uint32_t smem_u32(const void* p) {
    uint32_t a;
    asm("{ .reg .u64 t; cvta.to.shared.u64 t, %1; cvt.u32.u64 %0, t; }"
        : "=r"(a) : "l"(p));
    return a;
}
__device__ __forceinline__ void ldm_x4(uint32_t* r, uint32_t addr) {
    asm volatile("ldmatrix.sync.aligned.m8n8.x4.shared.b16 {%0,%1,%2,%3}, [%4];"
        : "=r"(r[0]), "=r"(r[1]), "=r"(r[2]), "=r"(r[3]) : "r"(addr));
}
__device__ __forceinline__ void ldm_x2(uint32_t* r, uint32_t addr) {
    asm volatile("ldmatrix.sync.aligned.m8n8.x2.shared.b16 {%0,%1}, [%2];"
        : "=r"(r[0]), "=r"(r[1]) : "r"(addr));
}
__device__ __forceinline__ void ldm_x4_trans(uint32_t* r, uint32_t addr) {
    asm volatile("ldmatrix.sync.aligned.m8n8.x4.trans.shared.b16 {%0,%1,%2,%3}, [%4];"
        : "=r"(r[0]), "=r"(r[1]), "=r"(r[2]), "=r"(r[3]) : "r"(addr));
}
__device__ __forceinline__ void mma_fp16(float* c, const uint32_t* a, const uint32_t* b) {
    asm volatile("mma.sync.aligned.m16n8k16.row.col.f32.f16.f16.f32 "
        "{%0,%1,%2,%3}, {%4,%5,%6,%7}, {%8,%9}, {%0,%1,%2,%3};"
        : "+f"(c[0]), "+f"(c[1]), "+f"(c[2]), "+f"(c[3])
        : "r"(a[0]), "r"(a[1]), "r"(a[2]), "r"(a[3]), "r"(b[0]), "r"(b[1]));
}
__device__ __forceinline__ void cp16(uint32_t s, const void* g) {
    asm volatile("cp.async.cg.shared.global [%0], [%1], 16;" :: "r"(s), "l"(g));
}
#define CP_COMMIT() asm volatile("cp.async.commit_group;" ::: "memory")
#define CP_WAIT1()  asm volatile("cp.async.wait_group 1;" ::: "memory")
#define CP_WAIT0()  asm volatile("cp.async.wait_group 0;" ::: "memory")

// ======================= prep: f2h convert + zero accumulators ==============
#define NX4  (MROWS*CC/4)     // 6291456
#define NWQ4 (K3C*CC/4)       // 442368
#define NWP4 (CC*CC/4)        // 147456
__global__ void prep_kernel(const float* __restrict__ x,
                            const float* __restrict__ wq,
                            const float* __restrict__ wp) {
    int i = blockIdx.x * blockDim.x + threadIdx.x;
    if (i < BB*HH*HD*HD) g_gram[i] = 0.0f;
    if (i < BHD) { g_nq[i] = 0.0f; g_nk[i] = 0.0f; }
    const float* src;
    __half* dst;
    int off;
    if (i < NX4) { src = x; dst = g_xh; off = i; }
    else if (i < NX4 + NWQ4) { src = wq; dst = g_wqkvh; off = i - NX4; }
    else if (i < NX4 + NWQ4 + NWP4) { src = wp; dst = g_wprojh; off = i - NX4 - NWQ4; }
    else return;
    float4 v = ((const float4*)src)[off];
    __half2 a = __float22half2_rn(make_float2(v.x, v.y));
    __half2 b = __float22half2_rn(make_float2(v.z, v.w));
    uint2 u;
    u.x = *reinterpret_cast<uint32_t*>(&a);
    u.y = *reinterpret_cast<uint32_t*>(&b);
    ((uint2*)dst)[off] = u;
}

// ======================= fp16 GEMM mainloop: 128x128, KC=64, 3-stage ========
#define PH 72
#define TSZH (128*PH*2)      // 18432 B
#define STAGEH (2*TSZH)      // 36864 B (A + B)
#define NSTG 3
#define DSMEMH (NSTG*STAGEH) // 110592 B
#define KCH 64
#define NCHH (CC/KCH)        // 12

__device__ __forceinline__ void issue_chunk(
    const __half* __restrict__ A, const __half* __restrict__ B,
    int m0, int n0, int k0, uint32_t st, int tid)
{
#pragma unroll
    for (int p = 0; p < 4; p++) {
        int slot = tid + p * 256;          // 0..1023
        int row = slot >> 3, c = slot & 7;
        cp16(st + row * (PH * 2) + c * 16,
             A + (size_t)(m0 + row) * CC + k0 + c * 8);
        cp16(st + TSZH + row * (PH * 2) + c * 16,
             B + (size_t)(n0 + row) * CC + k0 + c * 8);
    }
}

__device__ __forceinline__ void mma_mainloop_h(
    const __half* __restrict__ A, const __half* __restrict__ B,
    int m0, int n0, float acc[4][4][4], char* sm)
{
    const int tid = threadIdx.x;
    const int wid = tid >> 5, lane = tid & 31;
    const int wm = (wid >> 2) * 64;
    const int wn = (wid & 3) * 32;
    const uint32_t sbase = smem_u32(sm);
    const uint32_t a_l = (uint32_t)(wm + (lane & 15)) * (PH * 2) + ((lane >> 4) << 4);
    const uint32_t b_l = (uint32_t)(wn + (lane & 7) + ((lane >> 4) & 1) * 8) * (PH * 2)
                       + (((lane >> 3) & 1) << 4);

    issue_chunk(A, B, m0, n0, 0, sbase, tid);
    CP_COMMIT();
    issue_chunk(A, B, m0, n0, KCH, sbase + STAGEH, tid);
    CP_COMMIT();

    for (int c = 0; c < NCHH; c++) {
        if (c == NCHH - 1) { CP_WAIT0(); } else { CP_WAIT1(); }
        __syncthreads();
        if (c + 2 < NCHH) {
            issue_chunk(A, B, m0, n0, (c + 2) * KCH,
                        sbase + (uint32_t)((c + 2) % NSTG) * STAGEH, tid);
            CP_COMMIT();
        }
        const uint32_t st = sbase + (uint32_t)(c % NSTG) * STAGEH;
#pragma unroll
        for (int kk = 0; kk < 4; kk++) {
            uint32_t ah[4][4], bh[2][4];
#pragma unroll
            for (int i = 0; i < 4; i++)
                ldm_x4(ah[i], st + a_l + kk * 32 + i * 16 * (PH * 2));
#pragma unroll
            for (int j = 0; j < 2; j++)
                ldm_x4(bh[j], st + TSZH + b_l + kk * 32 + j * 16 * (PH * 2));
#pragma unroll
            for (int i = 0; i < 4; i++)
#pragma unroll
                for (int j4 = 0; j4 < 4; j4++)
                    mma_fp16(acc[i][j4], ah[i], &bh[j4 >> 1][(j4 & 1) * 2]);
        }
    }
}

// ---- QKV GEMM: M = qkv features, N = tokens; scatter fp16 + fused norm ----
__global__ __launch_bounds__(256, 2) void gemm_qkv_mma(void) {
    extern __shared__ char sm[];
    const int m0 = blockIdx.x * 128;
    const int n0 = blockIdx.y * 128;
    float acc[4][4][4];
#pragma unroll
    for (int i = 0; i < 4; i++)
#pragma unroll
        for (int j = 0; j < 4; j++)
#pragma unroll
            for (int r = 0; r < 4; r++) acc[i][j][r] = 0.0f;

    mma_mainloop_h(g_wqkvh, g_xh, m0, n0, acc, sm);

    const int tid = threadIdx.x;
    const int wid = tid >> 5, lane = tid & 31;
    const int wm = (wid >> 2) * 64, wn = (wid & 3) * 32;
    const int b = n0 >> 12;
    const int ntk = (n0 & (NN - 1)) + wn + (lane & 3) * 2;
#pragma unroll
    for (int i = 0; i < 4; i++) {
#pragma unroll
        for (int half = 0; half < 2; half++) {
            int f = m0 + wm + i * 16 + (lane >> 2) + half * 8;
            int t = f / CC;
            int rem = f - t * CC;
            int h = rem / HD, d = rem - h * HD;
            __half* dst = (t == 0) ? g_qh : (t == 1) ? g_kh : g_vh;
            __half* rowp = dst + ((size_t)(b * HH + h) * HD + d) * NN;
            float ssum = 0.0f;
#pragma unroll
            for (int j4 = 0; j4 < 4; j4++) {
                float v0 = acc[i][j4][half * 2], v1 = acc[i][j4][half * 2 + 1];
                *(__half2*)&rowp[ntk + j4 * 8] = __floats2half2_rn(v0, v1);
                ssum += v0 * v0 + v1 * v1;
            }
            if (t < 2) {
                ssum += __shfl_xor_sync(0xffffffff, ssum, 1);
                ssum += __shfl_xor_sync(0xffffffff, ssum, 2);
                if ((lane & 3) == 0)
                    atomicAdd(&((t == 0) ? g_nq : g_nk)[(b * HH + h) * HD + d], ssum);
            }
        }
    }
}

// ---- Proj GEMM: M = tokens (g_aoh), N = out features; out fp32 coalesced ----
__global__ __launch_bounds__(256, 2) void gemm_proj_mma(
    const float* __restrict__ bias, float* __restrict__ out)
{
    extern __shared__ char sm[];
    const int n0 = blockIdx.x * 128;
    const int m0 = blockIdx.y * 128;
    float acc[4][4][4];
#pragma unroll
    for (int i = 0; i < 4; i++)
#pragma unroll
        for (int j = 0; j < 4; j++)
#pragma unroll
            for (int r = 0; r < 4; r++) acc[i][j][r] = 0.0f;

    mma_mainloop_h(g_aoh, g_wprojh, m0, n0, acc, sm);

    const int tid = threadIdx.x;
    const int wid = tid >> 5, lane = tid & 31;
    const int wm = (wid >> 2) * 64, wn = (wid & 3) * 32;
    float2 bv[4];
#pragma unroll
    for (int j4 = 0; j4 < 4; j4++)
        bv[j4] = *(const float2*)&bias[n0 + wn + j4 * 8 + (lane & 3) * 2];
#pragma unroll
    for (int i = 0; i < 4; i++) {
#pragma unroll
        for (int half = 0; half < 2; half++) {
            int tok = m0 + wm + i * 16 + (lane >> 2) + half * 8;
            float* rowp = out + (size_t)tok * CC + n0 + wn + (lane & 3) * 2;
#pragma unroll
            for (int j4 = 0; j4 < 4; j4++) {
                *(float2*)&rowp[j4 * 8] =
                    make_float2(acc[i][j4][half * 2] + bv[j4].x,
                                acc[i][j4][half * 2 + 1] + bv[j4].y);
            }
        }
    }
}

// ---------------- Gram via mma (ksplit 16, register-prefetch) ----------------
#define GP 72
__global__ __launch_bounds__(256) void gram_mma() {
    const int bh = blockIdx.y;
    const int kseg = blockIdx.x;
    const __half* qb = g_qh + (size_t)bh * HD * NN;
    const __half* kb = g_kh + (size_t)bh * HD * NN;
    __shared__ __half qs[96 * GP];
    __shared__ __half ks[96 * GP];
    const int tid = threadIdx.x;
    const int wid = tid >> 5, lane = tid & 31;
    const int wm = (wid >> 2) * 48;
    const int wn = (wid & 3) * 24;
    const uint32_t qsb = smem_u32(qs), ksb = smem_u32(ks);
    const uint32_t a_base = qsb + ((wm + (lane & 15)) * GP + (lane >> 4) * 8) * 2;
    const uint32_t b_base = ksb + ((wn + (lane & 7)) * GP + ((lane >> 3) & 1) * 8) * 2;

    float acc[3][3][4];
#pragma unroll
    for (int i = 0; i < 3; i++)
#pragma unroll
        for (int j = 0; j < 3; j++)
#pragma unroll
            for (int r = 0; r < 4; r++) acc[i][j][r] = 0.0f;

    uint4 rg[6];
#pragma unroll
    for (int l = 0; l < 6; l++) {
        int idx = l * 256 + tid;
        int row = idx >> 4, s = idx & 15;
        rg[l] = (s < 8)
            ? *(const uint4*)&qb[(size_t)row * NN + kseg * 256 + s * 8]
            : *(const uint4*)&kb[(size_t)row * NN + kseg * 256 + (s - 8) * 8];
    }

    for (int it = 0; it < 4; it++) {
#pragma unroll
        for (int l = 0; l < 6; l++) {
            int idx = l * 256 + tid;
            int row = idx >> 4, s = idx & 15;
            if (s < 8) *(uint4*)&qs[row * GP + s * 8] = rg[l];
            else       *(uint4*)&ks[row * GP + (s - 8) * 8] = rg[l];
        }
        __syncthreads();
        if (it < 3) {
            int k0 = kseg * 256 + (it + 1) * 64;
#pragma unroll
            for (int l = 0; l < 6; l++) {
                int idx = l * 256 + tid;
                int row = idx >> 4, s = idx & 15;
                rg[l] = (s < 8)
                    ? *(const uint4*)&qb[(size_t)row * NN + k0 + s * 8]
                    : *(const uint4*)&kb[(size_t)row * NN + k0 + (s - 8) * 8];
            }
        }
#pragma unroll
        for (int kk = 0; kk < 4; kk++) {
            uint32_t a[3][4], bfr[3][2];
#pragma unroll
            for (int i = 0; i < 3; i++)
                ldm_x4(a[i], a_base + i * 16 * GP * 2 + kk * 32);
#pragma unroll
            for (int j = 0; j < 3; j++)
                ldm_x2(bfr[j], b_base + j * 8 * GP * 2 + kk * 32);
#pragma unroll
            for (int i = 0; i < 3; i++)
#pragma unroll
                for (int j = 0; j < 3; j++)
                    mma_fp16(acc[i][j], a[i], bfr[j]);
        }
        __syncthreads();
    }
    float* G = g_gram + (size_t)bh * HD * HD;
#pragma unroll
    for (int i = 0; i < 3; i++) {
        int d = wm + i * 16 + (lane >> 2);
#pragma unroll
        for (int j = 0; j < 3; j++) {
            int e = wn + j * 8 + (lane & 3) * 2;
            atomicAdd(&G[d * HD + e],       acc[i][j][0]);
            atomicAdd(&G[d * HD + e + 1],   acc[i][j][1]);
            atomicAdd(&G[(d + 8) * HD + e],     acc[i][j][2]);
            atomicAdd(&G[(d + 8) * HD + e + 1], acc[i][j][3]);
        }
    }
}

// ---------------- scale + softmax, warp-per-row, emit fp16 attn ------------
__global__ void softmax_kernel(const float* __restrict__ temp) {
    const int bh = blockIdx.x;
    const int h = bh & (HH - 1);
    const int wid = threadIdx.x >> 5, lane = threadIdx.x & 31;
    const int d = blockIdx.y * 8 + wid;            // grid.y = 12, 8 warps/block
    const float* row = g_gram + (size_t)bh * HD * HD + d * HD;
    __half* orow = g_attn + (size_t)bh * HD * HD + d * HD;
    const float nq = fmaxf(sqrtf(fmaxf(g_nq[bh * HD + d], 0.0f)), 1e-12f);
    const float scale = temp[h] / nq;

    float v[3];
    float mx = -1e30f;
#pragma unroll
    for (int j = 0; j < 3; j++) {
        int e = lane + j * 32;
        float rk = fmaxf(sqrtf(fmaxf(g_nk[bh * HD + e], 0.0f)), 1e-12f);
        v[j] = row[e] * scale / rk;
        mx = fmaxf(mx, v[j]);
    }
#pragma unroll
    for (int o = 16; o; o >>= 1) mx = fmaxf(mx, __shfl_xor_sync(0xffffffff, mx, o));
    float s = 0.0f;
#pragma unroll
    for (int j = 0; j < 3; j++) {
        v[j] = expf(v[j] - mx);
        s += v[j];
    }
#pragma unroll
    for (int o = 16; o; o >>= 1) s += __shfl_xor_sync(0xffffffff, s, o);
    float inv = 1.0f / s;
#pragma unroll
    for (int j = 0; j < 3; j++) orow[lane + j * 32] = __float2half(v[j] * inv);
}

// ---------------- AV via mma, smem-staged coalesced output (R14 version) ----
#define AP 104   // attn smem pitch (halves)
#define VP 136   // v smem pitch (halves)
#define OPD 104  // output stage pitch (halves), [n][d]
#define AVSM (96*AP*2 + 96*VP*2)   // 46080 B; output stage (128*OPD*2=26624) aliases
__global__ __launch_bounds__(256) void av_mma() {
    const int bh = blockIdx.y;
    const int n0 = blockIdx.x * 128;
    const int b = bh >> 3, h = bh & 7;
    __shared__ __align__(16) char smbuf[AVSM];
    __half* as_t = (__half*)smbuf;                 // [96][AP]
    __half* vs_t = (__half*)(smbuf + 96 * AP * 2); // [96][VP]
    const int tid = threadIdx.x;
    const int wid = tid >> 5, lane = tid & 31;
    const int wm = (wid >> 2) * 48;
    const int wn = (wid & 3) * 32;

    const __half* at = g_attn + (size_t)bh * HD * HD;
#pragma unroll
    for (int l = 0; l < 5; l++) {
        int idx = l * 256 + tid;
        if (idx < 1152) {
            int row = idx / 12, c = idx % 12;
            *(uint4*)&as_t[row * AP + c * 8] = *(const uint4*)&at[row * HD + c * 8];
        }
    }
    const __half* vb = g_vh + (size_t)bh * HD * NN;
#pragma unroll
    for (int l = 0; l < 6; l++) {
        int idx = l * 256 + tid;
        int row = idx >> 4, c = idx & 15;
        *(uint4*)&vs_t[row * VP + c * 8] = *(const uint4*)&vb[(size_t)row * NN + n0 + c * 8];
    }
    __syncthreads();

    const uint32_t asb = smem_u32(as_t), vsb = smem_u32(vs_t);
    const uint32_t a_base = asb + ((wm + (lane & 15)) * AP + (lane >> 4) * 8) * 2;
    const uint32_t b_roff = ((lane & 7) + ((lane >> 3) & 1) * 8) * VP * 2;
    const uint32_t b_coff = (wn + ((lane >> 4) & 1) * 8) * 2;

    float acc[3][4][4];
#pragma unroll
    for (int i = 0; i < 3; i++)
#pragma unroll
        for (int j = 0; j < 4; j++)
#pragma unroll
            for (int r = 0; r < 4; r++) acc[i][j][r] = 0.0f;

#pragma unroll
    for (int kk = 0; kk < 6; kk++) {
        uint32_t a[3][4], bt[2][4];
#pragma unroll
        for (int i = 0; i < 3; i++)
            ldm_x4(a[i], a_base + i * 16 * AP * 2 + kk * 32);
#pragma unroll
        for (int j = 0; j < 2; j++)
            ldm_x4_trans(bt[j], vsb + (kk * 16) * VP * 2 + b_roff + b_coff + j * 32);
#pragma unroll
        for (int i = 0; i < 3; i++)
#pragma unroll
            for (int jn = 0; jn < 4; jn++)
                mma_fp16(acc[i][jn], a[i], &bt[jn >> 1][(jn & 1) * 2]);
    }

    __syncthreads();
    __half* ot = (__half*)smbuf;   // [128][OPD]
#pragma unroll
    for (int i = 0; i < 3; i++) {
#pragma unroll
        for (int half = 0; half < 2; half++) {
            int d = wm + i * 16 + (lane >> 2) + half * 8;
#pragma unroll
            for (int jn = 0; jn < 4; jn++) {
                int nl = wn + jn * 8 + (lane & 3) * 2;
                ot[nl * OPD + d]       = __float2half(acc[i][jn][half * 2]);
                ot[(nl + 1) * OPD + d] = __float2half(acc[i][jn][half * 2 + 1]);
            }
        }
    }
    __syncthreads();
#pragma unroll
    for (int l = 0; l < 6; l++) {
        int idx = l * 256 + tid;           // 0..1535 (128 rows x 12 oct)
        int row = idx / 12, c = idx % 12;
        *(uint4*)&g_aoh[((size_t)(b * NN + n0 + row)) * CC + h * HD + c * 8] =
            *(uint4*)&ot[row * OPD + c * 8];
    }
}

// ---------------- launch ----------------
extern "C" void kernel_launch(void* const* d_in, const int* in_sizes, int n_in,
                              void* d_out, int out_size)
{
    const float* x      = (const float*)d_in[0];
    const float* w_qkv  = (const float*)d_in[1];
    const float* temp   = (const float*)d_in[2];
    const float* w_proj = (const float*)d_in[3];
    const float* b_proj = (const float*)d_in[4];
    float* out = (float*)d_out;

    cudaFuncSetAttribute(gemm_qkv_mma, cudaFuncAttributeMaxDynamicSharedMemorySize, DSMEMH);
    cudaFuncSetAttribute(gemm_proj_mma, cudaFuncAttributeMaxDynamicSharedMemorySize, DSMEMH);

    prep_kernel<<<(NX4 + NWQ4 + NWP4 + 511) / 512, 512>>>(x, w_qkv, w_proj);
    gemm_qkv_mma<<<dim3(K3C / 128, MROWS / 128), 256, DSMEMH>>>();
    gram_mma<<<dim3(16, BB * HH), 256>>>();
    softmax_kernel<<<dim3(BB * HH, 12), 256>>>(temp);
    av_mma<<<dim3(NN / 128, BB * HH), 256>>>();
    gemm_proj_mma<<<dim3(CC / 128, MROWS / 128), 256, DSMEMH>>>(b_proj, out);
}